// round 8
// baseline (speedup 1.0000x reference)
#include <cuda_runtime.h>
#include <cuda_fp16.h>
#include <cstdint>

#define N_B   4
#define L_SEQ 2048
#define N_H   16
#define D_H   32
#define DIM   512
#define CHUNK 32
#define N_CHUNK (L_SEQ / CHUNK)     // 64
#define TOT_ROWS (N_B * L_SEQ)      // 8192

// ---------------- device scratch (allocation-free rule) ----------------
__device__ float g_Q[TOT_ROWS * DIM];
__device__ float g_K[TOT_ROWS * DIM];
__device__ float g_V[TOT_ROWS * DIM];
__device__ float g_S[N_B * N_H * N_CHUNK * D_H * D_H];

// fp16 operands
__device__ __half hQ[TOT_ROWS * DIM];
__device__ __half hK[TOT_ROWS * DIM];
__device__ __half hW[3][DIM * DIM];

// ---------------- helpers ----------------
__device__ __forceinline__ uint32_t smem_u32(const void* p) {
    uint32_t a;
    asm("{ .reg .u64 t; cvta.to.shared.u64 t, %1; cvt.u32.u64 %0, t; }" : "=r"(a) : "l"(p));
    return a;
}
__device__ __forceinline__ void cp16(uint32_t dst, const void* src) {
    asm volatile("cp.async.cg.shared.global [%0], [%1], 16;" :: "r"(dst), "l"(src));
}
__device__ __forceinline__ void cp_commit() { asm volatile("cp.async.commit_group;" ::: "memory"); }
template<int N> __device__ __forceinline__ void cp_wait() {
    asm volatile("cp.async.wait_group %0;" :: "n"(N) : "memory");
}
__device__ __forceinline__ void ldsm4(uint32_t* r, uint32_t a) {
    asm volatile("ldmatrix.sync.aligned.m8n8.x4.shared.b16 {%0,%1,%2,%3}, [%4];"
                 : "=r"(r[0]), "=r"(r[1]), "=r"(r[2]), "=r"(r[3]) : "r"(a));
}
__device__ __forceinline__ void mma16816(float* d, const uint32_t* a, uint32_t b0, uint32_t b1) {
    asm volatile(
        "mma.sync.aligned.m16n8k16.row.col.f32.f16.f16.f32 "
        "{%0,%1,%2,%3}, {%4,%5,%6,%7}, {%8,%9}, {%0,%1,%2,%3};"
        : "+f"(d[0]), "+f"(d[1]), "+f"(d[2]), "+f"(d[3])
        : "r"(a[0]), "r"(a[1]), "r"(a[2]), "r"(a[3]), "r"(b0), "r"(b1));
}

// ---------------------------------------------------------------------------
// Kernel 0: fp32 -> fp16
// ---------------------------------------------------------------------------
#define NQ4 (TOT_ROWS * DIM / 4)
#define NW4 (DIM * DIM / 4)

__global__ __launch_bounds__(256) void convert_kernel(
    const float* __restrict__ q, const float* __restrict__ k,
    const float* __restrict__ wq, const float* __restrict__ wk,
    const float* __restrict__ wv)
{
    int idx = blockIdx.x * 256 + threadIdx.x;
    const float* src;
    __half* dst;
    int rel;
    if (idx < NQ4)          { src = q;  dst = hQ;    rel = idx; }
    else if (idx < 2 * NQ4) { src = k;  dst = hK;    rel = idx - NQ4; }
    else {
        int t = idx - 2 * NQ4;
        int w = t / NW4;
        rel = t - w * NW4;
        src = (w == 0) ? wq : (w == 1 ? wk : wv);
        dst = hW[w];
    }
    float4 v = reinterpret_cast<const float4*>(src)[rel];
    reinterpret_cast<__half2*>(dst)[rel * 2] =
        make_half2(__float2half_rn(v.x), __float2half_rn(v.y));
    reinterpret_cast<__half2*>(dst)[rel * 2 + 1] =
        make_half2(__float2half_rn(v.z), __float2half_rn(v.w));
}

// ---------------------------------------------------------------------------
// Kernel 1: HMMA projection GEMM (fp16 single pass).
// CTA 128x128, 8 warps of 64x32, BK=64, 3-stage pipeline, 1 sync/chunk.
// ---------------------------------------------------------------------------
#define SR 72                         // smem row stride in halfwords (144B)
#define TILE_HW (128 * SR)
#define TILE_B  (TILE_HW * 2)         // 18432 B
#define SMEM_BYTES (6 * TILE_B)       // A x3, B x3 = 110592

__global__ __launch_bounds__(256, 2) void proj_mma_kernel()
{
    extern __shared__ char smem_raw[];
    const uint32_t sb = smem_u32(smem_raw);
    const int tid  = threadIdx.x;
    const int wid  = tid >> 5;
    const int lane = tid & 31;
    const int warp_m = wid & 1;
    const int warp_n = wid >> 1;

    const int z  = blockIdx.z;
    const int bm = blockIdx.y * 128;
    const int bn = blockIdx.x * 128;
    const __half* A = (z == 0) ? hQ : hK;
    const __half* B = hW[z];
    float* O = (z == 0) ? g_Q : (z == 1 ? g_K : g_V);

    auto tA = [&](int buf) { return sb + (uint32_t)buf * TILE_B; };
    auto tB = [&](int buf) { return sb + (uint32_t)(3 + buf) * TILE_B; };

    auto prefetch = [&](int c, int buf) {
        const int k0 = c * 64;
        #pragma unroll
        for (int i = 0; i < 4; i++) {
            int idx = tid + 256 * i;
            int row = idx >> 3, seg = idx & 7;
            uint32_t doff = (uint32_t)(row * SR + seg * 8) * 2;
            cp16(tA(buf) + doff, A + (size_t)(bm + row) * DIM + k0 + seg * 8);
            cp16(tB(buf) + doff, B + (size_t)(bn + row) * DIM + k0 + seg * 8);
        }
        cp_commit();
    };

    float acc[4][4][4] = {};
    prefetch(0, 0);
    prefetch(1, 1);

    const int jA = lane >> 3;
    const int rA = lane & 7;

    for (int c = 0; c < 8; c++) {
        const int buf = c % 3;
        if (c + 1 < 8) { cp_wait<1>(); } else { cp_wait<0>(); }
        __syncthreads();
        // prefetch c+2 into buf (c+2)%3 == (c-1)%3 — freed: all warps are past
        // the sync above, hence done computing chunk c-1.
        if (c + 2 < 8) prefetch(c + 2, (c + 2) % 3);

        #pragma unroll
        for (int ks = 0; ks < 4; ks++) {
            uint32_t fA[4][4], fB[2][4];
            #pragma unroll
            for (int mt = 0; mt < 4; mt++) {
                uint32_t off = (uint32_t)((warp_m * 64 + mt * 16 + (jA & 1) * 8 + rA) * SR
                                          + ks * 16 + (jA >> 1) * 8) * 2;
                ldsm4(fA[mt], tA(buf) + off);
            }
            #pragma unroll
            for (int g = 0; g < 2; g++) {
                uint32_t off = (uint32_t)((warp_n * 32 + g * 16 + (jA & 1) * 8 + rA) * SR
                                          + ks * 16 + (jA >> 1) * 8) * 2;
                ldsm4(fB[g], tB(buf) + off);
            }
            #pragma unroll
            for (int mt = 0; mt < 4; mt++)
                #pragma unroll
                for (int nt = 0; nt < 4; nt++) {
                    int g = nt >> 1, s = nt & 1;
                    mma16816(acc[mt][nt], fA[mt], fB[g][s], fB[g][s + 2]);
                }
        }
    }

    // Epilogue: per-row softmax over this warp's 32-col head (z<2), store fp32.
    const int qlane = lane & 3;
    #pragma unroll
    for (int mt = 0; mt < 4; mt++) {
        #pragma unroll
        for (int rh = 0; rh < 2; rh++) {
            float v[4][2];
            #pragma unroll
            for (int nt = 0; nt < 4; nt++) {
                v[nt][0] = acc[mt][nt][2 * rh + 0];
                v[nt][1] = acc[mt][nt][2 * rh + 1];
            }
            if (z < 2) {
                float mx = v[0][0];
                #pragma unroll
                for (int nt = 0; nt < 4; nt++) {
                    mx = fmaxf(mx, v[nt][0]);
                    mx = fmaxf(mx, v[nt][1]);
                }
                mx = fmaxf(mx, __shfl_xor_sync(0xffffffffu, mx, 1));
                mx = fmaxf(mx, __shfl_xor_sync(0xffffffffu, mx, 2));
                float s = 0.f;
                #pragma unroll
                for (int nt = 0; nt < 4; nt++) {
                    v[nt][0] = expf(v[nt][0] - mx);
                    v[nt][1] = expf(v[nt][1] - mx);
                    s += v[nt][0] + v[nt][1];
                }
                s += __shfl_xor_sync(0xffffffffu, s, 1);
                s += __shfl_xor_sync(0xffffffffu, s, 2);
                float inv = 1.f / s;
                #pragma unroll
                for (int nt = 0; nt < 4; nt++) { v[nt][0] *= inv; v[nt][1] *= inv; }
            }
            int row = bm + warp_m * 64 + mt * 16 + (lane >> 2) + rh * 8;
            #pragma unroll
            for (int nt = 0; nt < 4; nt++) {
                int col = bn + warp_n * 32 + nt * 8 + 2 * qlane;
                *reinterpret_cast<float2*>(&O[(size_t)row * DIM + col]) =
                    make_float2(v[nt][0], v[nt][1]);
            }
        }
    }
}

// ---------------------------------------------------------------------------
// Kernel 2: FUSED per-chunk KV sums + exclusive prefix scan.
// One block per (n,h); running S[32][32] in registers (4 floats/thread);
// writes exclusive prefix to g_S before accumulating each chunk.
// 3-stage cp.async pipeline, 1 sync/chunk.
// ---------------------------------------------------------------------------
#define CS_ROW 36                    // smem row stride in floats (144B)

__global__ __launch_bounds__(256) void chunkscan_kernel()
{
    __shared__ float Ks[3][CHUNK][CS_ROW];
    __shared__ float Vs[3][CHUNK][CS_ROW];

    const int nh = blockIdx.x;       // 0..63
    const int n = nh >> 4, h = nh & 15;
    const int tid = threadIdx.x;
    const int d  = tid >> 3;         // 0..31
    const int e0 = (tid & 7) * 4;    // 0,4,...,28

    const float* Kbase = g_K + (size_t)n * L_SEQ * DIM + h * D_H;
    const float* Vbase = g_V + (size_t)n * L_SEQ * DIM + h * D_H;
    float* Sout = g_S + (size_t)nh * N_CHUNK * D_H * D_H;

    auto prefetch = [&](int c, int buf) {
        // 32 rows x 32 floats = 32 x 2 segs of 16B per tensor
        int l = tid >> 3, seg = tid & 7;   // seg 0..7 but only 0..1 used per tensor
        // map 256 threads -> 64 cp16 per tensor: threads with seg<2
        if (seg < 2) {
            uint32_t doff = (uint32_t)(l * CS_ROW + seg * 4) * 4;
            cp16(smem_u32(&Ks[buf][0][0]) + doff,
                 Kbase + (size_t)(c * CHUNK + l) * DIM + seg * 4);
            cp16(smem_u32(&Vs[buf][0][0]) + doff,
                 Vbase + (size_t)(c * CHUNK + l) * DIM + seg * 4);
        } else {
            // remaining threads: cover cols 8..31 (segs 2..7)
            uint32_t doff = (uint32_t)(l * CS_ROW + seg * 4) * 4;
            cp16(smem_u32(&Ks[buf][0][0]) + doff,
                 Kbase + (size_t)(c * CHUNK + l) * DIM + seg * 4);
            cp16(smem_u32(&Vs[buf][0][0]) + doff,
                 Vbase + (size_t)(c * CHUNK + l) * DIM + seg * 4);
        }
        cp_commit();
    };

    float run[4] = {0.f, 0.f, 0.f, 0.f};

    prefetch(0, 0);
    prefetch(1, 1);

    for (int c = 0; c < N_CHUNK; c++) {
        const int buf = c % 3;
        if (c + 1 < N_CHUNK) { cp_wait<1>(); } else { cp_wait<0>(); }
        __syncthreads();
        if (c + 2 < N_CHUNK) prefetch(c + 2, (c + 2) % 3);

        // write exclusive prefix for chunk c
        float* dst = Sout + (size_t)c * D_H * D_H + d * D_H + e0;
        *reinterpret_cast<float4*>(dst) = make_float4(run[0], run[1], run[2], run[3]);

        // accumulate chunk c: run[e] += sum_j K[j][d] * V[j][e]
        #pragma unroll
        for (int j = 0; j < CHUNK; j++) {
            float kv = Ks[buf][j][d];
            float4 v4 = *reinterpret_cast<const float4*>(&Vs[buf][j][e0]);
            run[0] = fmaf(kv, v4.x, run[0]);
            run[1] = fmaf(kv, v4.y, run[1]);
            run[2] = fmaf(kv, v4.z, run[2]);
            run[3] = fmaf(kv, v4.w, run[3]);
        }
    }
}

// ---------------------------------------------------------------------------
// Kernel 4: per-chunk output. 128 thr, 2 rows per thread; d-major K.
// ---------------------------------------------------------------------------
__global__ __launch_bounds__(128) void out_kernel(float* __restrict__ out)
{
    const int b = blockIdx.x;
    const int c = b & (N_CHUNK - 1);
    const int h = (b >> 6) & (N_H - 1);
    const int n = b >> 10;

    __shared__ float Qs[CHUNK][33];
    __shared__ float Kt[D_H][36];
    __shared__ float Vs[CHUNK][D_H];
    __shared__ float Sp[D_H][D_H];
    __shared__ float Am[CHUNK][33];

    const int tid = threadIdx.x;
    const int tx  = tid & 7;
    const int ty  = tid >> 3;
    const int j0  = tx * 4;

    #pragma unroll
    for (int rr = 0; rr < 2; rr++) {
        int l = ty + rr * 16;
        size_t base = (size_t)(n * L_SEQ + c * CHUNK + l) * DIM + h * D_H + j0;
        float4 q4 = *reinterpret_cast<const float4*>(&g_Q[base]);
        Qs[l][j0 + 0] = q4.x; Qs[l][j0 + 1] = q4.y; Qs[l][j0 + 2] = q4.z; Qs[l][j0 + 3] = q4.w;
        float4 k4 = *reinterpret_cast<const float4*>(&g_K[base]);
        Kt[j0 + 0][l] = k4.x; Kt[j0 + 1][l] = k4.y; Kt[j0 + 2][l] = k4.z; Kt[j0 + 3][l] = k4.w;
        *reinterpret_cast<float4*>(&Vs[l][j0]) = *reinterpret_cast<const float4*>(&g_V[base]);
        size_t sb2 = (size_t)((n * N_H + h) * N_CHUNK + c) * D_H * D_H + l * D_H + j0;
        *reinterpret_cast<float4*>(&Sp[l][j0]) = *reinterpret_cast<const float4*>(&g_S[sb2]);
    }
    __syncthreads();

    const int r0 = ty, r1 = ty + 16;

    float a0[4] = {}, a1[4] = {};
    #pragma unroll
    for (int d = 0; d < D_H; d++) {
        float q0 = Qs[r0][d];
        float q1 = Qs[r1][d];
        float4 k4 = *reinterpret_cast<const float4*>(&Kt[d][j0]);
        a0[0] = fmaf(q0, k4.x, a0[0]); a0[1] = fmaf(q0, k4.y, a0[1]);
        a0[2] = fmaf(q0, k4.z, a0[2]); a0[3] = fmaf(q0, k4.w, a0[3]);
        a1[0] = fmaf(q1, k4.x, a1[0]); a1[1] = fmaf(q1, k4.y, a1[1]);
        a1[2] = fmaf(q1, k4.z, a1[2]); a1[3] = fmaf(q1, k4.w, a1[3]);
    }
    #pragma unroll
    for (int jj = 0; jj < 4; jj++) {
        Am[r0][j0 + jj] = (j0 + jj <= r0) ? a0[jj] : 0.f;
        Am[r1][j0 + jj] = (j0 + jj <= r1) ? a1[jj] : 0.f;
    }
    __syncthreads();

    const int e0 = j0;
    float o0[4] = {}, o1[4] = {};
    #pragma unroll
    for (int d = 0; d < D_H; d++) {
        float q0 = Qs[r0][d];
        float q1 = Qs[r1][d];
        float4 s4 = *reinterpret_cast<const float4*>(&Sp[d][e0]);
        o0[0] = fmaf(q0, s4.x, o0[0]); o0[1] = fmaf(q0, s4.y, o0[1]);
        o0[2] = fmaf(q0, s4.z, o0[2]); o0[3] = fmaf(q0, s4.w, o0[3]);
        o1[0] = fmaf(q1, s4.x, o1[0]); o1[1] = fmaf(q1, s4.y, o1[1]);
        o1[2] = fmaf(q1, s4.z, o1[2]); o1[3] = fmaf(q1, s4.w, o1[3]);
    }
    #pragma unroll
    for (int j = 0; j < CHUNK; j++) {
        float m0 = Am[r0][j];
        float m1 = Am[r1][j];
        float4 v4 = *reinterpret_cast<const float4*>(&Vs[j][e0]);
        o0[0] = fmaf(m0, v4.x, o0[0]); o0[1] = fmaf(m0, v4.y, o0[1]);
        o0[2] = fmaf(m0, v4.z, o0[2]); o0[3] = fmaf(m0, v4.w, o0[3]);
        o1[0] = fmaf(m1, v4.x, o1[0]); o1[1] = fmaf(m1, v4.y, o1[1]);
        o1[2] = fmaf(m1, v4.z, o1[2]); o1[3] = fmaf(m1, v4.w, o1[3]);
    }
    size_t ob0 = (size_t)(n * L_SEQ + c * CHUNK + r0) * DIM + h * D_H + e0;
    size_t ob1 = (size_t)(n * L_SEQ + c * CHUNK + r1) * DIM + h * D_H + e0;
    *reinterpret_cast<float4*>(&out[ob0]) = make_float4(o0[0], o0[1], o0[2], o0[3]);
    *reinterpret_cast<float4*>(&out[ob1]) = make_float4(o1[0], o1[1], o1[2], o1[3]);
}

// ---------------------------------------------------------------------------
extern "C" void kernel_launch(void* const* d_in, const int* in_sizes, int n_in,
                              void* d_out, int out_size)
{
    const float* query = (const float*)d_in[0];
    const float* key   = (const float*)d_in[1];
    const float* Wq    = (const float*)d_in[2];
    const float* Wk    = (const float*)d_in[3];
    const float* Wv    = (const float*)d_in[4];
    float* out = (float*)d_out;

    cudaFuncSetAttribute(proj_mma_kernel,
                         cudaFuncAttributeMaxDynamicSharedMemorySize, SMEM_BYTES);

    int conv_blocks = (2 * NQ4 + 3 * NW4) / 256;
    convert_kernel<<<conv_blocks, 256>>>(query, key, Wq, Wk, Wv);

    dim3 gp(DIM / 128, TOT_ROWS / 128, 3);      // (4, 64, 3) = 768 CTAs
    proj_mma_kernel<<<gp, 256, SMEM_BYTES>>>();

    chunkscan_kernel<<<N_B * N_H, 256>>>();
    out_kernel<<<N_B * N_H * N_CHUNK, 128>>>(out);
}

// round 9
// speedup vs baseline: 1.3453x; 1.3453x over previous
#include <cuda_runtime.h>
#include <cuda_fp16.h>
#include <cstdint>

#define N_B   4
#define L_SEQ 2048
#define N_H   16
#define D_H   32
#define DIM   512
#define CHUNK 32
#define N_CHUNK (L_SEQ / CHUNK)     // 64
#define TOT_ROWS (N_B * L_SEQ)      // 8192

// ---------------- device scratch (allocation-free rule) ----------------
__device__ float g_Q[TOT_ROWS * DIM];
__device__ float g_K[TOT_ROWS * DIM];
__device__ float g_V[TOT_ROWS * DIM];
__device__ float g_S[N_B * N_H * N_CHUNK * D_H * D_H];

// fp16 operands
__device__ __half hQ[TOT_ROWS * DIM];
__device__ __half hK[TOT_ROWS * DIM];
__device__ __half hW[3][DIM * DIM];

// ---------------- helpers ----------------
__device__ __forceinline__ uint32_t smem_u32(const void* p) {
    uint32_t a;
    asm("{ .reg .u64 t; cvta.to.shared.u64 t, %1; cvt.u32.u64 %0, t; }" : "=r"(a) : "l"(p));
    return a;
}
__device__ __forceinline__ void cp16(uint32_t dst, const void* src) {
    asm volatile("cp.async.cg.shared.global [%0], [%1], 16;" :: "r"(dst), "l"(src));
}
__device__ __forceinline__ void cp_commit() { asm volatile("cp.async.commit_group;" ::: "memory"); }
template<int N> __device__ __forceinline__ void cp_wait() {
    asm volatile("cp.async.wait_group %0;" :: "n"(N) : "memory");
}
__device__ __forceinline__ void ldsm4(uint32_t* r, uint32_t a) {
    asm volatile("ldmatrix.sync.aligned.m8n8.x4.shared.b16 {%0,%1,%2,%3}, [%4];"
                 : "=r"(r[0]), "=r"(r[1]), "=r"(r[2]), "=r"(r[3]) : "r"(a));
}
__device__ __forceinline__ void mma16816(float* d, const uint32_t* a, uint32_t b0, uint32_t b1) {
    asm volatile(
        "mma.sync.aligned.m16n8k16.row.col.f32.f16.f16.f32 "
        "{%0,%1,%2,%3}, {%4,%5,%6,%7}, {%8,%9}, {%0,%1,%2,%3};"
        : "+f"(d[0]), "+f"(d[1]), "+f"(d[2]), "+f"(d[3])
        : "r"(a[0]), "r"(a[1]), "r"(a[2]), "r"(a[3]), "r"(b0), "r"(b1));
}

// ---------------------------------------------------------------------------
// Kernel 0: fp32 -> fp16
// ---------------------------------------------------------------------------
#define NQ4 (TOT_ROWS * DIM / 4)
#define NW4 (DIM * DIM / 4)

__global__ __launch_bounds__(256) void convert_kernel(
    const float* __restrict__ q, const float* __restrict__ k,
    const float* __restrict__ wq, const float* __restrict__ wk,
    const float* __restrict__ wv)
{
    int idx = blockIdx.x * 256 + threadIdx.x;
    const float* src;
    __half* dst;
    int rel;
    if (idx < NQ4)          { src = q;  dst = hQ;    rel = idx; }
    else if (idx < 2 * NQ4) { src = k;  dst = hK;    rel = idx - NQ4; }
    else {
        int t = idx - 2 * NQ4;
        int w = t / NW4;
        rel = t - w * NW4;
        src = (w == 0) ? wq : (w == 1 ? wk : wv);
        dst = hW[w];
    }
    float4 v = reinterpret_cast<const float4*>(src)[rel];
    reinterpret_cast<__half2*>(dst)[rel * 2] =
        make_half2(__float2half_rn(v.x), __float2half_rn(v.y));
    reinterpret_cast<__half2*>(dst)[rel * 2 + 1] =
        make_half2(__float2half_rn(v.z), __float2half_rn(v.w));
}

// ---------------------------------------------------------------------------
// Kernel 1: HMMA projection GEMM (fp16 single pass) — exact R7-measured schedule.
// CTA 128x128, 8 warps of 64x32, BK=64, 3-stage cp.async pipeline, 2 CTA/SM.
// ---------------------------------------------------------------------------
#define SR 72
#define TILE_HW (128 * SR)
#define TILE_B  (TILE_HW * 2)
#define SMEM_BYTES (6 * TILE_B)       // 110592

__global__ __launch_bounds__(256, 2) void proj_mma_kernel()
{
    extern __shared__ char smem_raw[];
    const uint32_t sb = smem_u32(smem_raw);
    const int tid  = threadIdx.x;
    const int wid  = tid >> 5;
    const int lane = tid & 31;
    const int warp_m = wid & 1;
    const int warp_n = wid >> 1;

    const int z  = blockIdx.z;
    const int bm = blockIdx.y * 128;
    const int bn = blockIdx.x * 128;
    const __half* A = (z == 0) ? hQ : hK;
    const __half* B = hW[z];
    float* O = (z == 0) ? g_Q : (z == 1 ? g_K : g_V);

    auto tA = [&](int buf) { return sb + (uint32_t)buf * TILE_B; };
    auto tB = [&](int buf) { return sb + (uint32_t)(3 + buf) * TILE_B; };

    auto prefetch = [&](int c, int buf) {
        const int k0 = c * 64;
        #pragma unroll
        for (int i = 0; i < 4; i++) {
            int idx = tid + 256 * i;
            int row = idx >> 3, seg = idx & 7;
            uint32_t doff = (uint32_t)(row * SR + seg * 8) * 2;
            cp16(tA(buf) + doff, A + (size_t)(bm + row) * DIM + k0 + seg * 8);
            cp16(tB(buf) + doff, B + (size_t)(bn + row) * DIM + k0 + seg * 8);
        }
        cp_commit();
    };

    float acc[4][4][4] = {};
    prefetch(0, 0);
    prefetch(1, 1);

    const int jA = lane >> 3;
    const int rA = lane & 7;

    for (int c = 0; c < 8; c++) {
        const int buf = c % 3;
        if (c + 2 < 8) {
            prefetch(c + 2, (c + 2) % 3);
            cp_wait<2>();
        } else if (c + 1 < 8) {
            cp_wait<1>();
        } else {
            cp_wait<0>();
        }
        __syncthreads();

        #pragma unroll
        for (int ks = 0; ks < 4; ks++) {
            uint32_t fA[4][4], fB[2][4];
            #pragma unroll
            for (int mt = 0; mt < 4; mt++) {
                uint32_t off = (uint32_t)((warp_m * 64 + mt * 16 + (jA & 1) * 8 + rA) * SR
                                          + ks * 16 + (jA >> 1) * 8) * 2;
                ldsm4(fA[mt], tA(buf) + off);
            }
            #pragma unroll
            for (int g = 0; g < 2; g++) {
                uint32_t off = (uint32_t)((warp_n * 32 + g * 16 + (jA & 1) * 8 + rA) * SR
                                          + ks * 16 + (jA >> 1) * 8) * 2;
                ldsm4(fB[g], tB(buf) + off);
            }
            #pragma unroll
            for (int mt = 0; mt < 4; mt++)
                #pragma unroll
                for (int nt = 0; nt < 4; nt++) {
                    int g = nt >> 1, s = nt & 1;
                    mma16816(acc[mt][nt], fA[mt], fB[g][s], fB[g][s + 2]);
                }
        }
        __syncthreads();
    }

    const int qlane = lane & 3;
    #pragma unroll
    for (int mt = 0; mt < 4; mt++) {
        #pragma unroll
        for (int rh = 0; rh < 2; rh++) {
            float v[4][2];
            #pragma unroll
            for (int nt = 0; nt < 4; nt++) {
                v[nt][0] = acc[mt][nt][2 * rh + 0];
                v[nt][1] = acc[mt][nt][2 * rh + 1];
            }
            if (z < 2) {
                float mx = v[0][0];
                #pragma unroll
                for (int nt = 0; nt < 4; nt++) {
                    mx = fmaxf(mx, v[nt][0]);
                    mx = fmaxf(mx, v[nt][1]);
                }
                mx = fmaxf(mx, __shfl_xor_sync(0xffffffffu, mx, 1));
                mx = fmaxf(mx, __shfl_xor_sync(0xffffffffu, mx, 2));
                float s = 0.f;
                #pragma unroll
                for (int nt = 0; nt < 4; nt++) {
                    v[nt][0] = expf(v[nt][0] - mx);
                    v[nt][1] = expf(v[nt][1] - mx);
                    s += v[nt][0] + v[nt][1];
                }
                s += __shfl_xor_sync(0xffffffffu, s, 1);
                s += __shfl_xor_sync(0xffffffffu, s, 2);
                float inv = 1.f / s;
                #pragma unroll
                for (int nt = 0; nt < 4; nt++) { v[nt][0] *= inv; v[nt][1] *= inv; }
            }
            int row = bm + warp_m * 64 + mt * 16 + (lane >> 2) + rh * 8;
            #pragma unroll
            for (int nt = 0; nt < 4; nt++) {
                int col = bn + warp_n * 32 + nt * 8 + 2 * qlane;
                *reinterpret_cast<float2*>(&O[(size_t)row * DIM + col]) =
                    make_float2(v[nt][0], v[nt][1]);
            }
        }
    }
}

// ---------------------------------------------------------------------------
// Kernel 2: per-chunk KV outer-product sums. 128 thr, 2 d-rows per thread.
// ---------------------------------------------------------------------------
__global__ __launch_bounds__(128) void chunk_kv_kernel()
{
    const int b = blockIdx.x;
    const int c = b & (N_CHUNK - 1);
    const int h = (b >> 6) & (N_H - 1);
    const int n = b >> 10;

    __shared__ float Ks[CHUNK][D_H];
    __shared__ float Vs[CHUNK][D_H];

    const int tid = threadIdx.x;
    const int tx  = tid & 7;
    const int ty  = tid >> 3;
    const int e0  = tx * 4;

    #pragma unroll
    for (int rr = 0; rr < 2; rr++) {
        int l = ty + rr * 16;
        size_t base = (size_t)(n * L_SEQ + c * CHUNK + l) * DIM + h * D_H + e0;
        *reinterpret_cast<float4*>(&Ks[l][e0]) = *reinterpret_cast<const float4*>(&g_K[base]);
        *reinterpret_cast<float4*>(&Vs[l][e0]) = *reinterpret_cast<const float4*>(&g_V[base]);
    }
    __syncthreads();

    float a0[4] = {}, a1[4] = {};
    #pragma unroll
    for (int l = 0; l < CHUNK; l++) {
        float k0 = Ks[l][ty];
        float k1 = Ks[l][ty + 16];
        float4 v4 = *reinterpret_cast<const float4*>(&Vs[l][e0]);
        a0[0] = fmaf(k0, v4.x, a0[0]); a0[1] = fmaf(k0, v4.y, a0[1]);
        a0[2] = fmaf(k0, v4.z, a0[2]); a0[3] = fmaf(k0, v4.w, a0[3]);
        a1[0] = fmaf(k1, v4.x, a1[0]); a1[1] = fmaf(k1, v4.y, a1[1]);
        a1[2] = fmaf(k1, v4.z, a1[2]); a1[3] = fmaf(k1, v4.w, a1[3]);
    }
    size_t sp = ((size_t)((n * N_H + h) * N_CHUNK + c) * D_H + ty) * D_H + e0;
    *reinterpret_cast<float4*>(&g_S[sp]) = make_float4(a0[0], a0[1], a0[2], a0[3]);
    *reinterpret_cast<float4*>(&g_S[sp + 16 * D_H]) = make_float4(a1[0], a1[1], a1[2], a1[3]);
}

// ---------------------------------------------------------------------------
// Kernel 3: exclusive prefix-scan over chunks, 8-wide batched loads for MLP.
// ---------------------------------------------------------------------------
__global__ __launch_bounds__(256) void scan_kernel()
{
    const int lane = blockIdx.x * blockDim.x + threadIdx.x;
    const int idx = lane & (D_H * D_H - 1);
    const int nh  = lane >> 10;
    float* base = &g_S[(size_t)nh * N_CHUNK * D_H * D_H + idx];
    float run = 0.f;
    #pragma unroll
    for (int b = 0; b < 8; b++) {
        float v[8];
        #pragma unroll
        for (int j = 0; j < 8; j++)
            v[j] = base[(size_t)(b * 8 + j) * (D_H * D_H)];
        #pragma unroll
        for (int j = 0; j < 8; j++) {
            base[(size_t)(b * 8 + j) * (D_H * D_H)] = run;
            run += v[j];
        }
    }
}

// ---------------------------------------------------------------------------
// Kernel 4: per-chunk output. 64 thr, 4 rows x 4 cols per thread; d-major K.
// ---------------------------------------------------------------------------
__global__ __launch_bounds__(64) void out_kernel(float* __restrict__ out)
{
    const int b = blockIdx.x;
    const int c = b & (N_CHUNK - 1);
    const int h = (b >> 6) & (N_H - 1);
    const int n = b >> 10;

    __shared__ float Qs[CHUNK][33];
    __shared__ float Kt[D_H][36];
    __shared__ float Vs[CHUNK][D_H];
    __shared__ float Sp[D_H][D_H];
    __shared__ float Am[CHUNK][33];

    const int tid = threadIdx.x;      // 0..63
    const int tx  = tid & 7;
    const int ty  = tid >> 3;         // 0..7
    const int j0  = tx * 4;

    #pragma unroll
    for (int rr = 0; rr < 4; rr++) {
        int l = ty + rr * 8;
        size_t base = (size_t)(n * L_SEQ + c * CHUNK + l) * DIM + h * D_H + j0;
        float4 q4 = *reinterpret_cast<const float4*>(&g_Q[base]);
        Qs[l][j0 + 0] = q4.x; Qs[l][j0 + 1] = q4.y; Qs[l][j0 + 2] = q4.z; Qs[l][j0 + 3] = q4.w;
        float4 k4 = *reinterpret_cast<const float4*>(&g_K[base]);
        Kt[j0 + 0][l] = k4.x; Kt[j0 + 1][l] = k4.y; Kt[j0 + 2][l] = k4.z; Kt[j0 + 3][l] = k4.w;
        *reinterpret_cast<float4*>(&Vs[l][j0]) = *reinterpret_cast<const float4*>(&g_V[base]);
        size_t sb2 = (size_t)((n * N_H + h) * N_CHUNK + c) * D_H * D_H + l * D_H + j0;
        *reinterpret_cast<float4*>(&Sp[l][j0]) = *reinterpret_cast<const float4*>(&g_S[sb2]);
    }
    __syncthreads();

    // A[r][j0..3] = Q_r . K_j for r = ty + 8*rr
    float a[4][4] = {};
    #pragma unroll
    for (int d = 0; d < D_H; d++) {
        float4 k4 = *reinterpret_cast<const float4*>(&Kt[d][j0]);
        #pragma unroll
        for (int rr = 0; rr < 4; rr++) {
            float q = Qs[ty + rr * 8][d];
            a[rr][0] = fmaf(q, k4.x, a[rr][0]);
            a[rr][1] = fmaf(q, k4.y, a[rr][1]);
            a[rr][2] = fmaf(q, k4.z, a[rr][2]);
            a[rr][3] = fmaf(q, k4.w, a[rr][3]);
        }
    }
    #pragma unroll
    for (int rr = 0; rr < 4; rr++) {
        int r = ty + rr * 8;
        #pragma unroll
        for (int jj = 0; jj < 4; jj++)
            Am[r][j0 + jj] = (j0 + jj <= r) ? a[rr][jj] : 0.f;
    }
    __syncthreads();

    const int e0 = j0;
    float o[4][4] = {};
    #pragma unroll
    for (int d = 0; d < D_H; d++) {
        float4 s4 = *reinterpret_cast<const float4*>(&Sp[d][e0]);
        #pragma unroll
        for (int rr = 0; rr < 4; rr++) {
            float q = Qs[ty + rr * 8][d];
            o[rr][0] = fmaf(q, s4.x, o[rr][0]);
            o[rr][1] = fmaf(q, s4.y, o[rr][1]);
            o[rr][2] = fmaf(q, s4.z, o[rr][2]);
            o[rr][3] = fmaf(q, s4.w, o[rr][3]);
        }
    }
    #pragma unroll
    for (int j = 0; j < CHUNK; j++) {
        float4 v4 = *reinterpret_cast<const float4*>(&Vs[j][e0]);
        #pragma unroll
        for (int rr = 0; rr < 4; rr++) {
            float m = Am[ty + rr * 8][j];
            o[rr][0] = fmaf(m, v4.x, o[rr][0]);
            o[rr][1] = fmaf(m, v4.y, o[rr][1]);
            o[rr][2] = fmaf(m, v4.z, o[rr][2]);
            o[rr][3] = fmaf(m, v4.w, o[rr][3]);
        }
    }
    #pragma unroll
    for (int rr = 0; rr < 4; rr++) {
        int r = ty + rr * 8;
        size_t ob = (size_t)(n * L_SEQ + c * CHUNK + r) * DIM + h * D_H + e0;
        *reinterpret_cast<float4*>(&out[ob]) =
            make_float4(o[rr][0], o[rr][1], o[rr][2], o[rr][3]);
    }
}

// ---------------------------------------------------------------------------
extern "C" void kernel_launch(void* const* d_in, const int* in_sizes, int n_in,
                              void* d_out, int out_size)
{
    const float* query = (const float*)d_in[0];
    const float* key   = (const float*)d_in[1];
    const float* Wq    = (const float*)d_in[2];
    const float* Wk    = (const float*)d_in[3];
    const float* Wv    = (const float*)d_in[4];
    float* out = (float*)d_out;

    cudaFuncSetAttribute(proj_mma_kernel,
                         cudaFuncAttributeMaxDynamicSharedMemorySize, SMEM_BYTES);

    int conv_blocks = (2 * NQ4 + 3 * NW4) / 256;
    convert_kernel<<<conv_blocks, 256>>>(query, key, Wq, Wk, Wv);

    dim3 gp(DIM / 128, TOT_ROWS / 128, 3);      // (4, 64, 3) = 768 CTAs
    proj_mma_kernel<<<gp, 256, SMEM_BYTES>>>();

    chunk_kv_kernel<<<N_B * N_H * N_CHUNK, 128>>>();
    scan_kernel<<<(N_B * N_H * D_H * D_H) / 256, 256>>>();
    out_kernel<<<N_B * N_H * N_CHUNK, 64>>>(out);
}

// round 10
// speedup vs baseline: 1.4928x; 1.1096x over previous
#include <cuda_runtime.h>
#include <cuda_fp16.h>
#include <cstdint>

#define N_B   4
#define L_SEQ 2048
#define N_H   16
#define D_H   32
#define DIM   512
#define CHUNK 32
#define N_CHUNK (L_SEQ / CHUNK)     // 64
#define TOT_ROWS (N_B * L_SEQ)      // 8192

// ---------------- device scratch (allocation-free rule) ----------------
__device__ float g_K[TOT_ROWS * DIM];
__device__ float g_V[TOT_ROWS * DIM];
__device__ float g_S[N_B * N_H * N_CHUNK * D_H * D_H];

// fp16 GEMM inputs
__device__ __half hQ[TOT_ROWS * DIM];
__device__ __half hK[TOT_ROWS * DIM];
__device__ __half hW[3][DIM * DIM];
// fp16 attention operands (post-softmax / projected)
__device__ __half g_Qh[TOT_ROWS * DIM];
__device__ __half g_Kh[TOT_ROWS * DIM];
__device__ __half g_Vh[TOT_ROWS * DIM];

// ---------------- helpers ----------------
__device__ __forceinline__ uint32_t smem_u32(const void* p) {
    uint32_t a;
    asm("{ .reg .u64 t; cvta.to.shared.u64 t, %1; cvt.u32.u64 %0, t; }" : "=r"(a) : "l"(p));
    return a;
}
__device__ __forceinline__ void cp16(uint32_t dst, const void* src) {
    asm volatile("cp.async.cg.shared.global [%0], [%1], 16;" :: "r"(dst), "l"(src));
}
__device__ __forceinline__ void cp_commit() { asm volatile("cp.async.commit_group;" ::: "memory"); }
template<int N> __device__ __forceinline__ void cp_wait() {
    asm volatile("cp.async.wait_group %0;" :: "n"(N) : "memory");
}
__device__ __forceinline__ void ldsm4(uint32_t* r, uint32_t a) {
    asm volatile("ldmatrix.sync.aligned.m8n8.x4.shared.b16 {%0,%1,%2,%3}, [%4];"
                 : "=r"(r[0]), "=r"(r[1]), "=r"(r[2]), "=r"(r[3]) : "r"(a));
}
__device__ __forceinline__ void ldsm4t(uint32_t* r, uint32_t a) {
    asm volatile("ldmatrix.sync.aligned.m8n8.x4.trans.shared.b16 {%0,%1,%2,%3}, [%4];"
                 : "=r"(r[0]), "=r"(r[1]), "=r"(r[2]), "=r"(r[3]) : "r"(a));
}
__device__ __forceinline__ void mma16816(float* d, const uint32_t* a, uint32_t b0, uint32_t b1) {
    asm volatile(
        "mma.sync.aligned.m16n8k16.row.col.f32.f16.f16.f32 "
        "{%0,%1,%2,%3}, {%4,%5,%6,%7}, {%8,%9}, {%0,%1,%2,%3};"
        : "+f"(d[0]), "+f"(d[1]), "+f"(d[2]), "+f"(d[3])
        : "r"(a[0]), "r"(a[1]), "r"(a[2]), "r"(a[3]), "r"(b0), "r"(b1));
}

// ---------------------------------------------------------------------------
// Kernel 0: fp32 -> fp16
// ---------------------------------------------------------------------------
#define NQ4 (TOT_ROWS * DIM / 4)
#define NW4 (DIM * DIM / 4)

__global__ __launch_bounds__(256) void convert_kernel(
    const float* __restrict__ q, const float* __restrict__ k,
    const float* __restrict__ wq, const float* __restrict__ wk,
    const float* __restrict__ wv)
{
    int idx = blockIdx.x * 256 + threadIdx.x;
    const float* src;
    __half* dst;
    int rel;
    if (idx < NQ4)          { src = q;  dst = hQ;    rel = idx; }
    else if (idx < 2 * NQ4) { src = k;  dst = hK;    rel = idx - NQ4; }
    else {
        int t = idx - 2 * NQ4;
        int w = t / NW4;
        rel = t - w * NW4;
        src = (w == 0) ? wq : (w == 1 ? wk : wv);
        dst = hW[w];
    }
    float4 v = reinterpret_cast<const float4*>(src)[rel];
    reinterpret_cast<__half2*>(dst)[rel * 2] =
        make_half2(__float2half_rn(v.x), __float2half_rn(v.y));
    reinterpret_cast<__half2*>(dst)[rel * 2 + 1] =
        make_half2(__float2half_rn(v.z), __float2half_rn(v.w));
}

// ---------------------------------------------------------------------------
// Kernel 1: HMMA projection GEMM (fp16 single pass), R7 schedule.
// Epilogue: z=0 -> g_Qh fp16 only; z=1 -> g_K fp32 + g_Kh; z=2 -> g_V + g_Vh.
// ---------------------------------------------------------------------------
#define SR 72
#define TILE_HW (128 * SR)
#define TILE_B  (TILE_HW * 2)
#define SMEM_BYTES (6 * TILE_B)       // 110592

__global__ __launch_bounds__(256, 2) void proj_mma_kernel()
{
    extern __shared__ char smem_raw[];
    const uint32_t sb = smem_u32(smem_raw);
    const int tid  = threadIdx.x;
    const int wid  = tid >> 5;
    const int lane = tid & 31;
    const int warp_m = wid & 1;
    const int warp_n = wid >> 1;

    const int z  = blockIdx.z;
    const int bm = blockIdx.y * 128;
    const int bn = blockIdx.x * 128;
    const __half* A = (z == 0) ? hQ : hK;
    const __half* B = hW[z];

    auto tA = [&](int buf) { return sb + (uint32_t)buf * TILE_B; };
    auto tB = [&](int buf) { return sb + (uint32_t)(3 + buf) * TILE_B; };

    auto prefetch = [&](int c, int buf) {
        const int k0 = c * 64;
        #pragma unroll
        for (int i = 0; i < 4; i++) {
            int idx = tid + 256 * i;
            int row = idx >> 3, seg = idx & 7;
            uint32_t doff = (uint32_t)(row * SR + seg * 8) * 2;
            cp16(tA(buf) + doff, A + (size_t)(bm + row) * DIM + k0 + seg * 8);
            cp16(tB(buf) + doff, B + (size_t)(bn + row) * DIM + k0 + seg * 8);
        }
        cp_commit();
    };

    float acc[4][4][4] = {};
    prefetch(0, 0);
    prefetch(1, 1);

    const int jA = lane >> 3;
    const int rA = lane & 7;

    for (int c = 0; c < 8; c++) {
        const int buf = c % 3;
        if (c + 2 < 8) {
            prefetch(c + 2, (c + 2) % 3);
            cp_wait<2>();
        } else if (c + 1 < 8) {
            cp_wait<1>();
        } else {
            cp_wait<0>();
        }
        __syncthreads();

        #pragma unroll
        for (int ks = 0; ks < 4; ks++) {
            uint32_t fA[4][4], fB[2][4];
            #pragma unroll
            for (int mt = 0; mt < 4; mt++) {
                uint32_t off = (uint32_t)((warp_m * 64 + mt * 16 + (jA & 1) * 8 + rA) * SR
                                          + ks * 16 + (jA >> 1) * 8) * 2;
                ldsm4(fA[mt], tA(buf) + off);
            }
            #pragma unroll
            for (int g = 0; g < 2; g++) {
                uint32_t off = (uint32_t)((warp_n * 32 + g * 16 + (jA & 1) * 8 + rA) * SR
                                          + ks * 16 + (jA >> 1) * 8) * 2;
                ldsm4(fB[g], tB(buf) + off);
            }
            #pragma unroll
            for (int mt = 0; mt < 4; mt++)
                #pragma unroll
                for (int nt = 0; nt < 4; nt++) {
                    int g = nt >> 1, s = nt & 1;
                    mma16816(acc[mt][nt], fA[mt], fB[g][s], fB[g][s + 2]);
                }
        }
        __syncthreads();
    }

    const int qlane = lane & 3;
    #pragma unroll
    for (int mt = 0; mt < 4; mt++) {
        #pragma unroll
        for (int rh = 0; rh < 2; rh++) {
            float v[4][2];
            #pragma unroll
            for (int nt = 0; nt < 4; nt++) {
                v[nt][0] = acc[mt][nt][2 * rh + 0];
                v[nt][1] = acc[mt][nt][2 * rh + 1];
            }
            if (z < 2) {
                float mx = v[0][0];
                #pragma unroll
                for (int nt = 0; nt < 4; nt++) {
                    mx = fmaxf(mx, v[nt][0]);
                    mx = fmaxf(mx, v[nt][1]);
                }
                mx = fmaxf(mx, __shfl_xor_sync(0xffffffffu, mx, 1));
                mx = fmaxf(mx, __shfl_xor_sync(0xffffffffu, mx, 2));
                float s = 0.f;
                #pragma unroll
                for (int nt = 0; nt < 4; nt++) {
                    v[nt][0] = expf(v[nt][0] - mx);
                    v[nt][1] = expf(v[nt][1] - mx);
                    s += v[nt][0] + v[nt][1];
                }
                s += __shfl_xor_sync(0xffffffffu, s, 1);
                s += __shfl_xor_sync(0xffffffffu, s, 2);
                float inv = 1.f / s;
                #pragma unroll
                for (int nt = 0; nt < 4; nt++) { v[nt][0] *= inv; v[nt][1] *= inv; }
            }
            int row = bm + warp_m * 64 + mt * 16 + (lane >> 2) + rh * 8;
            #pragma unroll
            for (int nt = 0; nt < 4; nt++) {
                int col = bn + warp_n * 32 + nt * 8 + 2 * qlane;
                size_t off = (size_t)row * DIM + col;
                __half2 hv = make_half2(__float2half_rn(v[nt][0]), __float2half_rn(v[nt][1]));
                if (z == 0) {
                    *reinterpret_cast<__half2*>(&g_Qh[off]) = hv;
                } else if (z == 1) {
                    *reinterpret_cast<float2*>(&g_K[off]) = make_float2(v[nt][0], v[nt][1]);
                    *reinterpret_cast<__half2*>(&g_Kh[off]) = hv;
                } else {
                    *reinterpret_cast<float2*>(&g_V[off]) = make_float2(v[nt][0], v[nt][1]);
                    *reinterpret_cast<__half2*>(&g_Vh[off]) = hv;
                }
            }
        }
    }
}

// ---------------------------------------------------------------------------
// Kernel 2: per-chunk KV outer-product sums (fp32). 128 thr, 2 d-rows/thread.
// ---------------------------------------------------------------------------
__global__ __launch_bounds__(128) void chunk_kv_kernel()
{
    const int b = blockIdx.x;
    const int c = b & (N_CHUNK - 1);
    const int h = (b >> 6) & (N_H - 1);
    const int n = b >> 10;

    __shared__ float Ks[CHUNK][D_H];
    __shared__ float Vs[CHUNK][D_H];

    const int tid = threadIdx.x;
    const int tx  = tid & 7;
    const int ty  = tid >> 3;
    const int e0  = tx * 4;

    #pragma unroll
    for (int rr = 0; rr < 2; rr++) {
        int l = ty + rr * 16;
        size_t base = (size_t)(n * L_SEQ + c * CHUNK + l) * DIM + h * D_H + e0;
        *reinterpret_cast<float4*>(&Ks[l][e0]) = *reinterpret_cast<const float4*>(&g_K[base]);
        *reinterpret_cast<float4*>(&Vs[l][e0]) = *reinterpret_cast<const float4*>(&g_V[base]);
    }
    __syncthreads();

    float a0[4] = {}, a1[4] = {};
    #pragma unroll
    for (int l = 0; l < CHUNK; l++) {
        float k0 = Ks[l][ty];
        float k1 = Ks[l][ty + 16];
        float4 v4 = *reinterpret_cast<const float4*>(&Vs[l][e0]);
        a0[0] = fmaf(k0, v4.x, a0[0]); a0[1] = fmaf(k0, v4.y, a0[1]);
        a0[2] = fmaf(k0, v4.z, a0[2]); a0[3] = fmaf(k0, v4.w, a0[3]);
        a1[0] = fmaf(k1, v4.x, a1[0]); a1[1] = fmaf(k1, v4.y, a1[1]);
        a1[2] = fmaf(k1, v4.z, a1[2]); a1[3] = fmaf(k1, v4.w, a1[3]);
    }
    size_t sp = ((size_t)((n * N_H + h) * N_CHUNK + c) * D_H + ty) * D_H + e0;
    *reinterpret_cast<float4*>(&g_S[sp]) = make_float4(a0[0], a0[1], a0[2], a0[3]);
    *reinterpret_cast<float4*>(&g_S[sp + 16 * D_H]) = make_float4(a1[0], a1[1], a1[2], a1[3]);
}

// ---------------------------------------------------------------------------
// Kernel 3: exclusive prefix-scan over chunks, 8-wide batched loads for MLP.
// ---------------------------------------------------------------------------
__global__ __launch_bounds__(256) void scan_kernel()
{
    const int lane = blockIdx.x * blockDim.x + threadIdx.x;
    const int idx = lane & (D_H * D_H - 1);
    const int nh  = lane >> 10;
    float* base = &g_S[(size_t)nh * N_CHUNK * D_H * D_H + idx];
    float run = 0.f;
    #pragma unroll
    for (int b = 0; b < 8; b++) {
        float v[8];
        #pragma unroll
        for (int j = 0; j < 8; j++)
            v[j] = base[(size_t)(b * 8 + j) * (D_H * D_H)];
        #pragma unroll
        for (int j = 0; j < 8; j++) {
            base[(size_t)(b * 8 + j) * (D_H * D_H)] = run;
            run += v[j];
        }
    }
}

// ---------------------------------------------------------------------------
// Kernel 4: tensor-core per-chunk output.
// 4 warps; warp (mw,nw) owns a 16x16 quadrant.
// Phase 1: A = Q K^T (mma), causal mask in-register, fp16 -> smem.
// Phase 2: out = Q*Sp + A*V, single fp32 accumulator chain; Sp/V B-fragments
//          via ldmatrix.trans on row-major tiles.
// ---------------------------------------------------------------------------
#define OS 40                         // smem row stride in halfs (80B)

__global__ __launch_bounds__(128) void out_mma_kernel(float* __restrict__ out)
{
    __shared__ __half Qs[32 * OS];
    __shared__ __half Ks[32 * OS];
    __shared__ __half Vs[32 * OS];
    __shared__ __half As[32 * OS];
    __shared__ __half Ss[32 * OS];

    const int b = blockIdx.x;
    const int c = b & (N_CHUNK - 1);
    const int h = (b >> 6) & (N_H - 1);
    const int n = b >> 10;

    const int tid  = threadIdx.x;
    const int wid  = tid >> 5;
    const int lane = tid & 31;
    const int mw = wid >> 1, nw = wid & 1;

    // ---- load tiles ----
    {
        int l = tid >> 2, seg = tid & 3;
        size_t gb = (size_t)(n * L_SEQ + c * CHUNK + l) * DIM + h * D_H + seg * 8;
        *reinterpret_cast<uint4*>(&Qs[l * OS + seg * 8]) =
            *reinterpret_cast<const uint4*>(&g_Qh[gb]);
        *reinterpret_cast<uint4*>(&Ks[l * OS + seg * 8]) =
            *reinterpret_cast<const uint4*>(&g_Kh[gb]);
        *reinterpret_cast<uint4*>(&Vs[l * OS + seg * 8]) =
            *reinterpret_cast<const uint4*>(&g_Vh[gb]);
        // Sp fp32 -> fp16
        const float* sp = g_S + (size_t)((n * N_H + h) * N_CHUNK + c) * D_H * D_H
                          + l * D_H + seg * 8;
        float4 x = *reinterpret_cast<const float4*>(sp);
        float4 y = *reinterpret_cast<const float4*>(sp + 4);
        __half2 p0 = make_half2(__float2half_rn(x.x), __float2half_rn(x.y));
        __half2 p1 = make_half2(__float2half_rn(x.z), __float2half_rn(x.w));
        __half2 p2 = make_half2(__float2half_rn(y.x), __float2half_rn(y.y));
        __half2 p3 = make_half2(__float2half_rn(y.z), __float2half_rn(y.w));
        __half2* d2 = reinterpret_cast<__half2*>(&Ss[l * OS + seg * 8]);
        d2[0] = p0; d2[1] = p1; d2[2] = p2; d2[3] = p3;
    }
    __syncthreads();

    const int jA = lane >> 3;
    const int rA = lane & 7;
    const int gr = lane >> 2;
    const int ql = lane & 3;

    // ---- phase 1: A = Q K^T ----
    float accA[2][4] = {};
    #pragma unroll
    for (int ks = 0; ks < 2; ks++) {
        uint32_t fQ[4], fK[4];
        ldsm4(fQ, smem_u32(&Qs[(mw * 16 + (jA & 1) * 8 + rA) * OS + ks * 16 + (jA >> 1) * 8]));
        ldsm4(fK, smem_u32(&Ks[(nw * 16 + (jA & 1) * 8 + rA) * OS + ks * 16 + (jA >> 1) * 8]));
        #pragma unroll
        for (int s = 0; s < 2; s++)
            mma16816(accA[s], fQ, fK[s], fK[s + 2]);
    }
    // mask (keep j<=i), cvt fp16, store to As
    {
        int row0 = mw * 16 + gr;
        int row1 = row0 + 8;
        #pragma unroll
        for (int s = 0; s < 2; s++) {
            int colb = nw * 16 + s * 8 + 2 * ql;
            float x0 = (colb     <= row0) ? accA[s][0] : 0.f;
            float x1 = (colb + 1 <= row0) ? accA[s][1] : 0.f;
            float x2 = (colb     <= row1) ? accA[s][2] : 0.f;
            float x3 = (colb + 1 <= row1) ? accA[s][3] : 0.f;
            *reinterpret_cast<__half2*>(&As[row0 * OS + colb]) =
                make_half2(__float2half_rn(x0), __float2half_rn(x1));
            *reinterpret_cast<__half2*>(&As[row1 * OS + colb]) =
                make_half2(__float2half_rn(x2), __float2half_rn(x3));
        }
    }
    __syncthreads();

    // ---- phase 2: out = Q*Sp + A*V ----
    float o[2][4] = {};
    #pragma unroll
    for (int ks = 0; ks < 2; ks++) {
        uint32_t fQ[4], fS[4];
        ldsm4(fQ, smem_u32(&Qs[(mw * 16 + (jA & 1) * 8 + rA) * OS + ks * 16 + (jA >> 1) * 8]));
        ldsm4t(fS, smem_u32(&Ss[(ks * 16 + (jA >> 1) * 8 + rA) * OS + nw * 16 + (jA & 1) * 8]));
        #pragma unroll
        for (int s = 0; s < 2; s++)
            mma16816(o[s], fQ, fS[s], fS[s + 2]);
    }
    #pragma unroll
    for (int ks = 0; ks < 2; ks++) {
        uint32_t fA[4], fV[4];
        ldsm4(fA, smem_u32(&As[(mw * 16 + (jA & 1) * 8 + rA) * OS + ks * 16 + (jA >> 1) * 8]));
        ldsm4t(fV, smem_u32(&Vs[(ks * 16 + (jA >> 1) * 8 + rA) * OS + nw * 16 + (jA & 1) * 8]));
        #pragma unroll
        for (int s = 0; s < 2; s++)
            mma16816(o[s], fA, fV[s], fV[s + 2]);
    }

    // ---- store fp32 ----
    {
        int row0 = mw * 16 + gr;
        #pragma unroll
        for (int s = 0; s < 2; s++) {
            int col = h * D_H + nw * 16 + s * 8 + 2 * ql;
            size_t ob0 = (size_t)(n * L_SEQ + c * CHUNK + row0) * DIM + col;
            size_t ob1 = (size_t)(n * L_SEQ + c * CHUNK + row0 + 8) * DIM + col;
            *reinterpret_cast<float2*>(&out[ob0]) = make_float2(o[s][0], o[s][1]);
            *reinterpret_cast<float2*>(&out[ob1]) = make_float2(o[s][2], o[s][3]);
        }
    }
}

// ---------------------------------------------------------------------------
extern "C" void kernel_launch(void* const* d_in, const int* in_sizes, int n_in,
                              void* d_out, int out_size)
{
    const float* query = (const float*)d_in[0];
    const float* key   = (const float*)d_in[1];
    const float* Wq    = (const float*)d_in[2];
    const float* Wk    = (const float*)d_in[3];
    const float* Wv    = (const float*)d_in[4];
    float* out = (float*)d_out;

    cudaFuncSetAttribute(proj_mma_kernel,
                         cudaFuncAttributeMaxDynamicSharedMemorySize, SMEM_BYTES);

    int conv_blocks = (2 * NQ4 + 3 * NW4) / 256;
    convert_kernel<<<conv_blocks, 256>>>(query, key, Wq, Wk, Wv);

    dim3 gp(DIM / 128, TOT_ROWS / 128, 3);      // (4, 64, 3) = 768 CTAs
    proj_mma_kernel<<<gp, 256, SMEM_BYTES>>>();

    chunk_kv_kernel<<<N_B * N_H * N_CHUNK, 128>>>();
    scan_kernel<<<(N_B * N_H * D_H * D_H) / 256, 256>>>();
    out_mma_kernel<<<N_B * N_H * N_CHUNK, 128>>>(out);
}

// round 11
// speedup vs baseline: 1.5930x; 1.0671x over previous
#include <cuda_runtime.h>
#include <cuda_fp16.h>
#include <cstdint>

#define N_B   4
#define L_SEQ 2048
#define N_H   16
#define D_H   32
#define DIM   512
#define CHUNK 32
#define N_CHUNK (L_SEQ / CHUNK)     // 64
#define TOT_ROWS (N_B * L_SEQ)      // 8192

// ---------------- device scratch (allocation-free rule) ----------------
__device__ float g_S[N_B * N_H * N_CHUNK * D_H * D_H];

// fp16 GEMM inputs
__device__ __half hQ[TOT_ROWS * DIM];
__device__ __half hK[TOT_ROWS * DIM];
__device__ __half hW[3][DIM * DIM];
// fp16 attention operands (post-softmax / projected) — sole K/V representation
__device__ __half g_Qh[TOT_ROWS * DIM];
__device__ __half g_Kh[TOT_ROWS * DIM];
__device__ __half g_Vh[TOT_ROWS * DIM];

// ---------------- helpers ----------------
__device__ __forceinline__ uint32_t smem_u32(const void* p) {
    uint32_t a;
    asm("{ .reg .u64 t; cvta.to.shared.u64 t, %1; cvt.u32.u64 %0, t; }" : "=r"(a) : "l"(p));
    return a;
}
__device__ __forceinline__ void cp16(uint32_t dst, const void* src) {
    asm volatile("cp.async.cg.shared.global [%0], [%1], 16;" :: "r"(dst), "l"(src));
}
__device__ __forceinline__ void cp_commit() { asm volatile("cp.async.commit_group;" ::: "memory"); }
template<int N> __device__ __forceinline__ void cp_wait() {
    asm volatile("cp.async.wait_group %0;" :: "n"(N) : "memory");
}
__device__ __forceinline__ void ldsm4(uint32_t* r, uint32_t a) {
    asm volatile("ldmatrix.sync.aligned.m8n8.x4.shared.b16 {%0,%1,%2,%3}, [%4];"
                 : "=r"(r[0]), "=r"(r[1]), "=r"(r[2]), "=r"(r[3]) : "r"(a));
}
__device__ __forceinline__ void ldsm4t(uint32_t* r, uint32_t a) {
    asm volatile("ldmatrix.sync.aligned.m8n8.x4.trans.shared.b16 {%0,%1,%2,%3}, [%4];"
                 : "=r"(r[0]), "=r"(r[1]), "=r"(r[2]), "=r"(r[3]) : "r"(a));
}
__device__ __forceinline__ void mma16816(float* d, const uint32_t* a, uint32_t b0, uint32_t b1) {
    asm volatile(
        "mma.sync.aligned.m16n8k16.row.col.f32.f16.f16.f32 "
        "{%0,%1,%2,%3}, {%4,%5,%6,%7}, {%8,%9}, {%0,%1,%2,%3};"
        : "+f"(d[0]), "+f"(d[1]), "+f"(d[2]), "+f"(d[3])
        : "r"(a[0]), "r"(a[1]), "r"(a[2]), "r"(a[3]), "r"(b0), "r"(b1));
}

// ---------------------------------------------------------------------------
// Kernel 0: fp32 -> fp16
// ---------------------------------------------------------------------------
#define NQ4 (TOT_ROWS * DIM / 4)
#define NW4 (DIM * DIM / 4)

__global__ __launch_bounds__(256) void convert_kernel(
    const float* __restrict__ q, const float* __restrict__ k,
    const float* __restrict__ wq, const float* __restrict__ wk,
    const float* __restrict__ wv)
{
    int idx = blockIdx.x * 256 + threadIdx.x;
    const float* src;
    __half* dst;
    int rel;
    if (idx < NQ4)          { src = q;  dst = hQ;    rel = idx; }
    else if (idx < 2 * NQ4) { src = k;  dst = hK;    rel = idx - NQ4; }
    else {
        int t = idx - 2 * NQ4;
        int w = t / NW4;
        rel = t - w * NW4;
        src = (w == 0) ? wq : (w == 1 ? wk : wv);
        dst = hW[w];
    }
    float4 v = reinterpret_cast<const float4*>(src)[rel];
    reinterpret_cast<__half2*>(dst)[rel * 2] =
        make_half2(__float2half_rn(v.x), __float2half_rn(v.y));
    reinterpret_cast<__half2*>(dst)[rel * 2 + 1] =
        make_half2(__float2half_rn(v.z), __float2half_rn(v.w));
}

// ---------------------------------------------------------------------------
// Kernel 1: HMMA projection GEMM (fp16 single pass), R7 schedule.
// Epilogue stores fp16 ONLY (g_Qh / g_Kh / g_Vh).
// ---------------------------------------------------------------------------
#define SR 72
#define TILE_HW (128 * SR)
#define TILE_B  (TILE_HW * 2)
#define SMEM_BYTES (6 * TILE_B)       // 110592

__global__ __launch_bounds__(256, 2) void proj_mma_kernel()
{
    extern __shared__ char smem_raw[];
    const uint32_t sb = smem_u32(smem_raw);
    const int tid  = threadIdx.x;
    const int wid  = tid >> 5;
    const int lane = tid & 31;
    const int warp_m = wid & 1;
    const int warp_n = wid >> 1;

    const int z  = blockIdx.z;
    const int bm = blockIdx.y * 128;
    const int bn = blockIdx.x * 128;
    const __half* A = (z == 0) ? hQ : hK;
    const __half* B = hW[z];
    __half* O = (z == 0) ? g_Qh : (z == 1 ? g_Kh : g_Vh);

    auto tA = [&](int buf) { return sb + (uint32_t)buf * TILE_B; };
    auto tB = [&](int buf) { return sb + (uint32_t)(3 + buf) * TILE_B; };

    auto prefetch = [&](int c, int buf) {
        const int k0 = c * 64;
        #pragma unroll
        for (int i = 0; i < 4; i++) {
            int idx = tid + 256 * i;
            int row = idx >> 3, seg = idx & 7;
            uint32_t doff = (uint32_t)(row * SR + seg * 8) * 2;
            cp16(tA(buf) + doff, A + (size_t)(bm + row) * DIM + k0 + seg * 8);
            cp16(tB(buf) + doff, B + (size_t)(bn + row) * DIM + k0 + seg * 8);
        }
        cp_commit();
    };

    float acc[4][4][4] = {};
    prefetch(0, 0);
    prefetch(1, 1);

    const int jA = lane >> 3;
    const int rA = lane & 7;

    for (int c = 0; c < 8; c++) {
        const int buf = c % 3;
        if (c + 2 < 8) {
            prefetch(c + 2, (c + 2) % 3);
            cp_wait<2>();
        } else if (c + 1 < 8) {
            cp_wait<1>();
        } else {
            cp_wait<0>();
        }
        __syncthreads();

        #pragma unroll
        for (int ks = 0; ks < 4; ks++) {
            uint32_t fA[4][4], fB[2][4];
            #pragma unroll
            for (int mt = 0; mt < 4; mt++) {
                uint32_t off = (uint32_t)((warp_m * 64 + mt * 16 + (jA & 1) * 8 + rA) * SR
                                          + ks * 16 + (jA >> 1) * 8) * 2;
                ldsm4(fA[mt], tA(buf) + off);
            }
            #pragma unroll
            for (int g = 0; g < 2; g++) {
                uint32_t off = (uint32_t)((warp_n * 32 + g * 16 + (jA & 1) * 8 + rA) * SR
                                          + ks * 16 + (jA >> 1) * 8) * 2;
                ldsm4(fB[g], tB(buf) + off);
            }
            #pragma unroll
            for (int mt = 0; mt < 4; mt++)
                #pragma unroll
                for (int nt = 0; nt < 4; nt++) {
                    int g = nt >> 1, s = nt & 1;
                    mma16816(acc[mt][nt], fA[mt], fB[g][s], fB[g][s + 2]);
                }
        }
        __syncthreads();
    }

    const int qlane = lane & 3;
    #pragma unroll
    for (int mt = 0; mt < 4; mt++) {
        #pragma unroll
        for (int rh = 0; rh < 2; rh++) {
            float v[4][2];
            #pragma unroll
            for (int nt = 0; nt < 4; nt++) {
                v[nt][0] = acc[mt][nt][2 * rh + 0];
                v[nt][1] = acc[mt][nt][2 * rh + 1];
            }
            if (z < 2) {
                float mx = v[0][0];
                #pragma unroll
                for (int nt = 0; nt < 4; nt++) {
                    mx = fmaxf(mx, v[nt][0]);
                    mx = fmaxf(mx, v[nt][1]);
                }
                mx = fmaxf(mx, __shfl_xor_sync(0xffffffffu, mx, 1));
                mx = fmaxf(mx, __shfl_xor_sync(0xffffffffu, mx, 2));
                float s = 0.f;
                #pragma unroll
                for (int nt = 0; nt < 4; nt++) {
                    v[nt][0] = expf(v[nt][0] - mx);
                    v[nt][1] = expf(v[nt][1] - mx);
                    s += v[nt][0] + v[nt][1];
                }
                s += __shfl_xor_sync(0xffffffffu, s, 1);
                s += __shfl_xor_sync(0xffffffffu, s, 2);
                float inv = 1.f / s;
                #pragma unroll
                for (int nt = 0; nt < 4; nt++) { v[nt][0] *= inv; v[nt][1] *= inv; }
            }
            int row = bm + warp_m * 64 + mt * 16 + (lane >> 2) + rh * 8;
            #pragma unroll
            for (int nt = 0; nt < 4; nt++) {
                int col = bn + warp_n * 32 + nt * 8 + 2 * qlane;
                *reinterpret_cast<__half2*>(&O[(size_t)row * DIM + col]) =
                    make_half2(__float2half_rn(v[nt][0]), __float2half_rn(v[nt][1]));
            }
        }
    }
}

// ---------------------------------------------------------------------------
// Kernel 2: per-chunk KV outer-product sums; reads fp16 K/V, fp32 accumulate.
// ---------------------------------------------------------------------------
__global__ __launch_bounds__(128) void chunk_kv_kernel()
{
    const int b = blockIdx.x;
    const int c = b & (N_CHUNK - 1);
    const int h = (b >> 6) & (N_H - 1);
    const int n = b >> 10;

    __shared__ float Ks[CHUNK][D_H];
    __shared__ float Vs[CHUNK][D_H];

    const int tid = threadIdx.x;
    const int tx  = tid & 7;
    const int ty  = tid >> 3;
    const int e0  = tx * 4;

    #pragma unroll
    for (int rr = 0; rr < 2; rr++) {
        int l = ty + rr * 16;
        size_t base = (size_t)(n * L_SEQ + c * CHUNK + l) * DIM + h * D_H + e0;
        __half2 k01 = *reinterpret_cast<const __half2*>(&g_Kh[base]);
        __half2 k23 = *reinterpret_cast<const __half2*>(&g_Kh[base + 2]);
        __half2 v01 = *reinterpret_cast<const __half2*>(&g_Vh[base]);
        __half2 v23 = *reinterpret_cast<const __half2*>(&g_Vh[base + 2]);
        Ks[l][e0 + 0] = __low2float(k01);  Ks[l][e0 + 1] = __high2float(k01);
        Ks[l][e0 + 2] = __low2float(k23);  Ks[l][e0 + 3] = __high2float(k23);
        Vs[l][e0 + 0] = __low2float(v01);  Vs[l][e0 + 1] = __high2float(v01);
        Vs[l][e0 + 2] = __low2float(v23);  Vs[l][e0 + 3] = __high2float(v23);
    }
    __syncthreads();

    float a0[4] = {}, a1[4] = {};
    #pragma unroll
    for (int l = 0; l < CHUNK; l++) {
        float k0 = Ks[l][ty];
        float k1 = Ks[l][ty + 16];
        float4 v4 = *reinterpret_cast<const float4*>(&Vs[l][e0]);
        a0[0] = fmaf(k0, v4.x, a0[0]); a0[1] = fmaf(k0, v4.y, a0[1]);
        a0[2] = fmaf(k0, v4.z, a0[2]); a0[3] = fmaf(k0, v4.w, a0[3]);
        a1[0] = fmaf(k1, v4.x, a1[0]); a1[1] = fmaf(k1, v4.y, a1[1]);
        a1[2] = fmaf(k1, v4.z, a1[2]); a1[3] = fmaf(k1, v4.w, a1[3]);
    }
    size_t sp = ((size_t)((n * N_H + h) * N_CHUNK + c) * D_H + ty) * D_H + e0;
    *reinterpret_cast<float4*>(&g_S[sp]) = make_float4(a0[0], a0[1], a0[2], a0[3]);
    *reinterpret_cast<float4*>(&g_S[sp + 16 * D_H]) = make_float4(a1[0], a1[1], a1[2], a1[3]);
}

// ---------------------------------------------------------------------------
// Kernel 3: exclusive prefix-scan; ALL 64 loads issued before any store (MLP=64).
// ---------------------------------------------------------------------------
__global__ __launch_bounds__(256) void scan_kernel()
{
    const int lane = blockIdx.x * blockDim.x + threadIdx.x;
    const int idx = lane & (D_H * D_H - 1);
    const int nh  = lane >> 10;
    float* base = &g_S[(size_t)nh * N_CHUNK * D_H * D_H + idx];
    float v[N_CHUNK];
    #pragma unroll
    for (int j = 0; j < N_CHUNK; j++)
        v[j] = base[(size_t)j * (D_H * D_H)];
    float run = 0.f;
    #pragma unroll
    for (int j = 0; j < N_CHUNK; j++) {
        base[(size_t)j * (D_H * D_H)] = run;
        run += v[j];
    }
}

// ---------------------------------------------------------------------------
// Kernel 4: tensor-core per-chunk output (unchanged from R10).
// ---------------------------------------------------------------------------
#define OS 40

__global__ __launch_bounds__(128) void out_mma_kernel(float* __restrict__ out)
{
    __shared__ __half Qs[32 * OS];
    __shared__ __half Ks[32 * OS];
    __shared__ __half Vs[32 * OS];
    __shared__ __half As[32 * OS];
    __shared__ __half Ss[32 * OS];

    const int b = blockIdx.x;
    const int c = b & (N_CHUNK - 1);
    const int h = (b >> 6) & (N_H - 1);
    const int n = b >> 10;

    const int tid  = threadIdx.x;
    const int wid  = tid >> 5;
    const int lane = tid & 31;
    const int mw = wid >> 1, nw = wid & 1;

    {
        int l = tid >> 2, seg = tid & 3;
        size_t gb = (size_t)(n * L_SEQ + c * CHUNK + l) * DIM + h * D_H + seg * 8;
        *reinterpret_cast<uint4*>(&Qs[l * OS + seg * 8]) =
            *reinterpret_cast<const uint4*>(&g_Qh[gb]);
        *reinterpret_cast<uint4*>(&Ks[l * OS + seg * 8]) =
            *reinterpret_cast<const uint4*>(&g_Kh[gb]);
        *reinterpret_cast<uint4*>(&Vs[l * OS + seg * 8]) =
            *reinterpret_cast<const uint4*>(&g_Vh[gb]);
        const float* sp = g_S + (size_t)((n * N_H + h) * N_CHUNK + c) * D_H * D_H
                          + l * D_H + seg * 8;
        float4 x = *reinterpret_cast<const float4*>(sp);
        float4 y = *reinterpret_cast<const float4*>(sp + 4);
        __half2* d2 = reinterpret_cast<__half2*>(&Ss[l * OS + seg * 8]);
        d2[0] = make_half2(__float2half_rn(x.x), __float2half_rn(x.y));
        d2[1] = make_half2(__float2half_rn(x.z), __float2half_rn(x.w));
        d2[2] = make_half2(__float2half_rn(y.x), __float2half_rn(y.y));
        d2[3] = make_half2(__float2half_rn(y.z), __float2half_rn(y.w));
    }
    __syncthreads();

    const int jA = lane >> 3;
    const int rA = lane & 7;
    const int gr = lane >> 2;
    const int ql = lane & 3;

    float accA[2][4] = {};
    #pragma unroll
    for (int ks = 0; ks < 2; ks++) {
        uint32_t fQ[4], fK[4];
        ldsm4(fQ, smem_u32(&Qs[(mw * 16 + (jA & 1) * 8 + rA) * OS + ks * 16 + (jA >> 1) * 8]));
        ldsm4(fK, smem_u32(&Ks[(nw * 16 + (jA & 1) * 8 + rA) * OS + ks * 16 + (jA >> 1) * 8]));
        #pragma unroll
        for (int s = 0; s < 2; s++)
            mma16816(accA[s], fQ, fK[s], fK[s + 2]);
    }
    {
        int row0 = mw * 16 + gr;
        int row1 = row0 + 8;
        #pragma unroll
        for (int s = 0; s < 2; s++) {
            int colb = nw * 16 + s * 8 + 2 * ql;
            float x0 = (colb     <= row0) ? accA[s][0] : 0.f;
            float x1 = (colb + 1 <= row0) ? accA[s][1] : 0.f;
            float x2 = (colb     <= row1) ? accA[s][2] : 0.f;
            float x3 = (colb + 1 <= row1) ? accA[s][3] : 0.f;
            *reinterpret_cast<__half2*>(&As[row0 * OS + colb]) =
                make_half2(__float2half_rn(x0), __float2half_rn(x1));
            *reinterpret_cast<__half2*>(&As[row1 * OS + colb]) =
                make_half2(__float2half_rn(x2), __float2half_rn(x3));
        }
    }
    __syncthreads();

    float o[2][4] = {};
    #pragma unroll
    for (int ks = 0; ks < 2; ks++) {
        uint32_t fQ[4], fS[4];
        ldsm4(fQ, smem_u32(&Qs[(mw * 16 + (jA & 1) * 8 + rA) * OS + ks * 16 + (jA >> 1) * 8]));
        ldsm4t(fS, smem_u32(&Ss[(ks * 16 + (jA >> 1) * 8 + rA) * OS + nw * 16 + (jA & 1) * 8]));
        #pragma unroll
        for (int s = 0; s < 2; s++)
            mma16816(o[s], fQ, fS[s], fS[s + 2]);
    }
    #pragma unroll
    for (int ks = 0; ks < 2; ks++) {
        uint32_t fA[4], fV[4];
        ldsm4(fA, smem_u32(&As[(mw * 16 + (jA & 1) * 8 + rA) * OS + ks * 16 + (jA >> 1) * 8]));
        ldsm4t(fV, smem_u32(&Vs[(ks * 16 + (jA >> 1) * 8 + rA) * OS + nw * 16 + (jA & 1) * 8]));
        #pragma unroll
        for (int s = 0; s < 2; s++)
            mma16816(o[s], fA, fV[s], fV[s + 2]);
    }

    {
        int row0 = mw * 16 + gr;
        #pragma unroll
        for (int s = 0; s < 2; s++) {
            int col = h * D_H + nw * 16 + s * 8 + 2 * ql;
            size_t ob0 = (size_t)(n * L_SEQ + c * CHUNK + row0) * DIM + col;
            size_t ob1 = (size_t)(n * L_SEQ + c * CHUNK + row0 + 8) * DIM + col;
            *reinterpret_cast<float2*>(&out[ob0]) = make_float2(o[s][0], o[s][1]);
            *reinterpret_cast<float2*>(&out[ob1]) = make_float2(o[s][2], o[s][3]);
        }
    }
}

// ---------------------------------------------------------------------------
extern "C" void kernel_launch(void* const* d_in, const int* in_sizes, int n_in,
                              void* d_out, int out_size)
{
    const float* query = (const float*)d_in[0];
    const float* key   = (const float*)d_in[1];
    const float* Wq    = (const float*)d_in[2];
    const float* Wk    = (const float*)d_in[3];
    const float* Wv    = (const float*)d_in[4];
    float* out = (float*)d_out;

    cudaFuncSetAttribute(proj_mma_kernel,
                         cudaFuncAttributeMaxDynamicSharedMemorySize, SMEM_BYTES);

    int conv_blocks = (2 * NQ4 + 3 * NW4) / 256;
    convert_kernel<<<conv_blocks, 256>>>(query, key, Wq, Wk, Wv);

    dim3 gp(DIM / 128, TOT_ROWS / 128, 3);      // (4, 64, 3) = 768 CTAs
    proj_mma_kernel<<<gp, 256, SMEM_BYTES>>>();

    chunk_kv_kernel<<<N_B * N_H * N_CHUNK, 128>>>();
    scan_kernel<<<(N_B * N_H * D_H * D_H) / 256, 256>>>();
    out_mma_kernel<<<N_B * N_H * N_CHUNK, 128>>>(out);
}

// round 14
// speedup vs baseline: 1.6117x; 1.0117x over previous
#include <cuda_runtime.h>
#include <cuda_fp16.h>
#include <cstdint>

#define N_B   4
#define L_SEQ 2048
#define N_H   16
#define D_H   32
#define DIM   512
#define CHUNK 32
#define N_CHUNK (L_SEQ / CHUNK)     // 64
#define TOT_ROWS (N_B * L_SEQ)      // 8192

// ---------------- device scratch (allocation-free rule) ----------------
__device__ float g_S[N_B * N_H * N_CHUNK * D_H * D_H];

// fp16 GEMM inputs
__device__ __half hQ[TOT_ROWS * DIM];
__device__ __half hK[TOT_ROWS * DIM];
__device__ __half hW[3][DIM * DIM];
// fp16 attention operands (post-softmax / projected)
__device__ __half g_Qh[TOT_ROWS * DIM];
__device__ __half g_Kh[TOT_ROWS * DIM];
__device__ __half g_Vh[TOT_ROWS * DIM];

// ---------------- helpers ----------------
__device__ __forceinline__ uint32_t smem_u32(const void* p) {
    uint32_t a;
    asm("{ .reg .u64 t; cvta.to.shared.u64 t, %1; cvt.u32.u64 %0, t; }" : "=r"(a) : "l"(p));
    return a;
}
__device__ __forceinline__ void cp16(uint32_t dst, const void* src) {
    asm volatile("cp.async.cg.shared.global [%0], [%1], 16;" :: "r"(dst), "l"(src));
}
__device__ __forceinline__ void cp_commit() { asm volatile("cp.async.commit_group;" ::: "memory"); }
template<int N> __device__ __forceinline__ void cp_wait() {
    asm volatile("cp.async.wait_group %0;" :: "n"(N) : "memory");
}
__device__ __forceinline__ void ldsm4(uint32_t* r, uint32_t a) {
    asm volatile("ldmatrix.sync.aligned.m8n8.x4.shared.b16 {%0,%1,%2,%3}, [%4];"
                 : "=r"(r[0]), "=r"(r[1]), "=r"(r[2]), "=r"(r[3]) : "r"(a));
}
__device__ __forceinline__ void ldsm4t(uint32_t* r, uint32_t a) {
    asm volatile("ldmatrix.sync.aligned.m8n8.x4.trans.shared.b16 {%0,%1,%2,%3}, [%4];"
                 : "=r"(r[0]), "=r"(r[1]), "=r"(r[2]), "=r"(r[3]) : "r"(a));
}
__device__ __forceinline__ void mma16816(float* d, const uint32_t* a, uint32_t b0, uint32_t b1) {
    asm volatile(
        "mma.sync.aligned.m16n8k16.row.col.f32.f16.f16.f32 "
        "{%0,%1,%2,%3}, {%4,%5,%6,%7}, {%8,%9}, {%0,%1,%2,%3};"
        : "+f"(d[0]), "+f"(d[1]), "+f"(d[2]), "+f"(d[3])
        : "r"(a[0]), "r"(a[1]), "r"(a[2]), "r"(a[3]), "r"(b0), "r"(b1));
}

// ---------------------------------------------------------------------------
// Kernel 0: fp32 -> fp16
// ---------------------------------------------------------------------------
#define NQ4 (TOT_ROWS * DIM / 4)
#define NW4 (DIM * DIM / 4)

__global__ __launch_bounds__(256) void convert_kernel(
    const float* __restrict__ q, const float* __restrict__ k,
    const float* __restrict__ wq, const float* __restrict__ wk,
    const float* __restrict__ wv)
{
    int idx = blockIdx.x * 256 + threadIdx.x;
    const float* src;
    __half* dst;
    int rel;
    if (idx < NQ4)          { src = q;  dst = hQ;    rel = idx; }
    else if (idx < 2 * NQ4) { src = k;  dst = hK;    rel = idx - NQ4; }
    else {
        int t = idx - 2 * NQ4;
        int w = t / NW4;
        rel = t - w * NW4;
        src = (w == 0) ? wq : (w == 1 ? wk : wv);
        dst = hW[w];
    }
    float4 v = reinterpret_cast<const float4*>(src)[rel];
    reinterpret_cast<__half2*>(dst)[rel * 2] =
        make_half2(__float2half_rn(v.x), __float2half_rn(v.y));
    reinterpret_cast<__half2*>(dst)[rel * 2 + 1] =
        make_half2(__float2half_rn(v.z), __float2half_rn(v.w));
}

// ---------------------------------------------------------------------------
// Kernel 1: HMMA projection GEMM (fp16 single pass), R7 schedule. fp16 out.
// ---------------------------------------------------------------------------
#define SR 72
#define TILE_HW (128 * SR)
#define TILE_B  (TILE_HW * 2)
#define SMEM_BYTES (6 * TILE_B)       // 110592

__global__ __launch_bounds__(256, 2) void proj_mma_kernel()
{
    extern __shared__ char smem_raw[];
    const uint32_t sb = smem_u32(smem_raw);
    const int tid  = threadIdx.x;
    const int wid  = tid >> 5;
    const int lane = tid & 31;
    const int warp_m = wid & 1;
    const int warp_n = wid >> 1;

    const int z  = blockIdx.z;
    const int bm = blockIdx.y * 128;
    const int bn = blockIdx.x * 128;
    const __half* A = (z == 0) ? hQ : hK;
    const __half* B = hW[z];
    __half* O = (z == 0) ? g_Qh : (z == 1 ? g_Kh : g_Vh);

    auto tA = [&](int buf) { return sb + (uint32_t)buf * TILE_B; };
    auto tB = [&](int buf) { return sb + (uint32_t)(3 + buf) * TILE_B; };

    auto prefetch = [&](int c, int buf) {
        const int k0 = c * 64;
        #pragma unroll
        for (int i = 0; i < 4; i++) {
            int idx = tid + 256 * i;
            int row = idx >> 3, seg = idx & 7;
            uint32_t doff = (uint32_t)(row * SR + seg * 8) * 2;
            cp16(tA(buf) + doff, A + (size_t)(bm + row) * DIM + k0 + seg * 8);
            cp16(tB(buf) + doff, B + (size_t)(bn + row) * DIM + k0 + seg * 8);
        }
        cp_commit();
    };

    float acc[4][4][4] = {};
    prefetch(0, 0);
    prefetch(1, 1);

    const int jA = lane >> 3;
    const int rA = lane & 7;

    for (int c = 0; c < 8; c++) {
        const int buf = c % 3;
        if (c + 2 < 8) {
            prefetch(c + 2, (c + 2) % 3);
            cp_wait<2>();
        } else if (c + 1 < 8) {
            cp_wait<1>();
        } else {
            cp_wait<0>();
        }
        __syncthreads();

        #pragma unroll
        for (int ks = 0; ks < 4; ks++) {
            uint32_t fA[4][4], fB[2][4];
            #pragma unroll
            for (int mt = 0; mt < 4; mt++) {
                uint32_t off = (uint32_t)((warp_m * 64 + mt * 16 + (jA & 1) * 8 + rA) * SR
                                          + ks * 16 + (jA >> 1) * 8) * 2;
                ldsm4(fA[mt], tA(buf) + off);
            }
            #pragma unroll
            for (int g = 0; g < 2; g++) {
                uint32_t off = (uint32_t)((warp_n * 32 + g * 16 + (jA & 1) * 8 + rA) * SR
                                          + ks * 16 + (jA >> 1) * 8) * 2;
                ldsm4(fB[g], tB(buf) + off);
            }
            #pragma unroll
            for (int mt = 0; mt < 4; mt++)
                #pragma unroll
                for (int nt = 0; nt < 4; nt++) {
                    int g = nt >> 1, s = nt & 1;
                    mma16816(acc[mt][nt], fA[mt], fB[g][s], fB[g][s + 2]);
                }
        }
        __syncthreads();
    }

    const int qlane = lane & 3;
    #pragma unroll
    for (int mt = 0; mt < 4; mt++) {
        #pragma unroll
        for (int rh = 0; rh < 2; rh++) {
            float v[4][2];
            #pragma unroll
            for (int nt = 0; nt < 4; nt++) {
                v[nt][0] = acc[mt][nt][2 * rh + 0];
                v[nt][1] = acc[mt][nt][2 * rh + 1];
            }
            if (z < 2) {
                float mx = v[0][0];
                #pragma unroll
                for (int nt = 0; nt < 4; nt++) {
                    mx = fmaxf(mx, v[nt][0]);
                    mx = fmaxf(mx, v[nt][1]);
                }
                mx = fmaxf(mx, __shfl_xor_sync(0xffffffffu, mx, 1));
                mx = fmaxf(mx, __shfl_xor_sync(0xffffffffu, mx, 2));
                float s = 0.f;
                #pragma unroll
                for (int nt = 0; nt < 4; nt++) {
                    v[nt][0] = expf(v[nt][0] - mx);
                    v[nt][1] = expf(v[nt][1] - mx);
                    s += v[nt][0] + v[nt][1];
                }
                s += __shfl_xor_sync(0xffffffffu, s, 1);
                s += __shfl_xor_sync(0xffffffffu, s, 2);
                float inv = 1.f / s;
                #pragma unroll
                for (int nt = 0; nt < 4; nt++) { v[nt][0] *= inv; v[nt][1] *= inv; }
            }
            int row = bm + warp_m * 64 + mt * 16 + (lane >> 2) + rh * 8;
            #pragma unroll
            for (int nt = 0; nt < 4; nt++) {
                int col = bn + warp_n * 32 + nt * 8 + 2 * qlane;
                *reinterpret_cast<__half2*>(&O[(size_t)row * DIM + col]) =
                    make_half2(__float2half_rn(v[nt][0]), __float2half_rn(v[nt][1]));
            }
        }
    }
}

// ---------------------------------------------------------------------------
// Kernel 2: per-chunk KV outer-product sums; reads fp16 K/V, fp32 accumulate.
// ---------------------------------------------------------------------------
__global__ __launch_bounds__(128) void chunk_kv_kernel()
{
    const int b = blockIdx.x;
    const int c = b & (N_CHUNK - 1);
    const int h = (b >> 6) & (N_H - 1);
    const int n = b >> 10;

    __shared__ float Ks[CHUNK][D_H];
    __shared__ float Vs[CHUNK][D_H];

    const int tid = threadIdx.x;
    const int tx  = tid & 7;
    const int ty  = tid >> 3;
    const int e0  = tx * 4;

    #pragma unroll
    for (int rr = 0; rr < 2; rr++) {
        int l = ty + rr * 16;
        size_t base = (size_t)(n * L_SEQ + c * CHUNK + l) * DIM + h * D_H + e0;
        __half2 k01 = *reinterpret_cast<const __half2*>(&g_Kh[base]);
        __half2 k23 = *reinterpret_cast<const __half2*>(&g_Kh[base + 2]);
        __half2 v01 = *reinterpret_cast<const __half2*>(&g_Vh[base]);
        __half2 v23 = *reinterpret_cast<const __half2*>(&g_Vh[base + 2]);
        Ks[l][e0 + 0] = __low2float(k01);  Ks[l][e0 + 1] = __high2float(k01);
        Ks[l][e0 + 2] = __low2float(k23);  Ks[l][e0 + 3] = __high2float(k23);
        Vs[l][e0 + 0] = __low2float(v01);  Vs[l][e0 + 1] = __high2float(v01);
        Vs[l][e0 + 2] = __low2float(v23);  Vs[l][e0 + 3] = __high2float(v23);
    }
    __syncthreads();

    float a0[4] = {}, a1[4] = {};
    #pragma unroll
    for (int l = 0; l < CHUNK; l++) {
        float k0 = Ks[l][ty];
        float k1 = Ks[l][ty + 16];
        float4 v4 = *reinterpret_cast<const float4*>(&Vs[l][e0]);
        a0[0] = fmaf(k0, v4.x, a0[0]); a0[1] = fmaf(k0, v4.y, a0[1]);
        a0[2] = fmaf(k0, v4.z, a0[2]); a0[3] = fmaf(k0, v4.w, a0[3]);
        a1[0] = fmaf(k1, v4.x, a1[0]); a1[1] = fmaf(k1, v4.y, a1[1]);
        a1[2] = fmaf(k1, v4.z, a1[2]); a1[3] = fmaf(k1, v4.w, a1[3]);
    }
    size_t sp = ((size_t)((n * N_H + h) * N_CHUNK + c) * D_H + ty) * D_H + e0;
    *reinterpret_cast<float4*>(&g_S[sp]) = make_float4(a0[0], a0[1], a0[2], a0[3]);
    *reinterpret_cast<float4*>(&g_S[sp + 16 * D_H]) = make_float4(a1[0], a1[1], a1[2], a1[3]);
}

// ---------------------------------------------------------------------------
// Kernel 3: exclusive prefix-scan, two-level: 4 threads per lane, 16 chunks
// each (fits registers), block-level segment-total exchange.
// ---------------------------------------------------------------------------
__global__ __launch_bounds__(256) void scan_kernel()
{
    __shared__ float tot[4][64];
    const int tid = threadIdx.x;
    const int seg = tid >> 6;              // 0..3
    const int ll  = tid & 63;
    const int lane = blockIdx.x * 64 + ll; // 0..65535
    const int idx = lane & (D_H * D_H - 1);
    const int nh  = lane >> 10;
    float* base = &g_S[(size_t)nh * N_CHUNK * D_H * D_H + idx];

    float v[16];
    #pragma unroll
    for (int j = 0; j < 16; j++)
        v[j] = base[(size_t)(seg * 16 + j) * (D_H * D_H)];
    float sum = 0.f;
    #pragma unroll
    for (int j = 0; j < 16; j++) sum += v[j];
    tot[seg][ll] = sum;
    __syncthreads();

    float run = 0.f;
    #pragma unroll
    for (int s = 0; s < 4; s++)
        if (s < seg) run += tot[s][ll];
    #pragma unroll
    for (int j = 0; j < 16; j++) {
        base[(size_t)(seg * 16 + j) * (D_H * D_H)] = run;
        run += v[j];
    }
}

// ---------------------------------------------------------------------------
// Kernel 4: tensor-core per-chunk output, register A-reuse (FA-style).
// 128 thr = 2 chunks x 2 warps; warp owns 16 rows x full 32 cols.
// A c-frags repacked in-register as A-operand of A*V; fQ reused both phases.
// One __syncthreads total.
// ---------------------------------------------------------------------------
#define OS 40

__global__ __launch_bounds__(128) void out_mma_kernel(float* __restrict__ out)
{
    __shared__ __half Qs[2][32 * OS];
    __shared__ __half Ks[2][32 * OS];
    __shared__ __half Vs[2][32 * OS];
    __shared__ __half Ss[2][32 * OS];

    const int g = blockIdx.x;             // 0..2047
    const int tid  = threadIdx.x;
    const int wid  = tid >> 5;
    const int lane = tid & 31;
    const int cw = wid >> 1;              // chunk slot 0/1
    const int mw = wid & 1;               // row half

    // ---- load both chunk tile sets ----
    {
        int l = tid >> 2, seg = tid & 3;
        #pragma unroll
        for (int ts = 0; ts < 2; ts++) {
            int gc = g * 2 + ts;
            int c = gc & (N_CHUNK - 1), h = (gc >> 6) & (N_H - 1), n = gc >> 10;
            size_t gb = (size_t)(n * L_SEQ + c * CHUNK + l) * DIM + h * D_H + seg * 8;
            *reinterpret_cast<uint4*>(&Qs[ts][l * OS + seg * 8]) =
                *reinterpret_cast<const uint4*>(&g_Qh[gb]);
            *reinterpret_cast<uint4*>(&Ks[ts][l * OS + seg * 8]) =
                *reinterpret_cast<const uint4*>(&g_Kh[gb]);
            *reinterpret_cast<uint4*>(&Vs[ts][l * OS + seg * 8]) =
                *reinterpret_cast<const uint4*>(&g_Vh[gb]);
            const float* sp = g_S + (size_t)((n * N_H + h) * N_CHUNK + c) * D_H * D_H
                              + l * D_H + seg * 8;
            float4 x = *reinterpret_cast<const float4*>(sp);
            float4 y = *reinterpret_cast<const float4*>(sp + 4);
            __half2* d2 = reinterpret_cast<__half2*>(&Ss[ts][l * OS + seg * 8]);
            d2[0] = make_half2(__float2half_rn(x.x), __float2half_rn(x.y));
            d2[1] = make_half2(__float2half_rn(x.z), __float2half_rn(x.w));
            d2[2] = make_half2(__float2half_rn(y.x), __float2half_rn(y.y));
            d2[3] = make_half2(__float2half_rn(y.z), __float2half_rn(y.w));
        }
    }
    __syncthreads();

    const int jA = lane >> 3;
    const int rA = lane & 7;
    const int gr = lane >> 2;
    const int ql = lane & 3;

    const int gc = g * 2 + cw;
    const int c = gc & (N_CHUNK - 1), h = (gc >> 6) & (N_H - 1), n = gc >> 10;

    // ---- phase 1: A = Q K^T (warp: rows mw*16.., all 32 cols) ----
    uint32_t fQ[2][4];
    float accA[2][2][4] = {};    // [kchunk(col half)][s][frag]
    #pragma unroll
    for (int ks = 0; ks < 2; ks++) {
        ldsm4(fQ[ks], smem_u32(&Qs[cw][(mw * 16 + (jA & 1) * 8 + rA) * OS
                                       + ks * 16 + (jA >> 1) * 8]));
        #pragma unroll
        for (int nh2 = 0; nh2 < 2; nh2++) {
            uint32_t fK[4];
            ldsm4(fK, smem_u32(&Ks[cw][(nh2 * 16 + (jA & 1) * 8 + rA) * OS
                                       + ks * 16 + (jA >> 1) * 8]));
            #pragma unroll
            for (int s = 0; s < 2; s++)
                mma16816(accA[nh2][s], fQ[ks], fK[s], fK[s + 2]);
        }
    }
    // causal mask + repack c-frags as A-operand frags (no smem round trip)
    const int row0 = mw * 16 + gr;
    const int row1 = row0 + 8;
    uint32_t aA[2][4];
    #pragma unroll
    for (int kc = 0; kc < 2; kc++) {
        #pragma unroll
        for (int s = 0; s < 2; s++) {
            int colb = kc * 16 + s * 8 + 2 * ql;
            float x0 = (colb     <= row0) ? accA[kc][s][0] : 0.f;
            float x1 = (colb + 1 <= row0) ? accA[kc][s][1] : 0.f;
            float x2 = (colb     <= row1) ? accA[kc][s][2] : 0.f;
            float x3 = (colb + 1 <= row1) ? accA[kc][s][3] : 0.f;
            __half2 p01 = make_half2(__float2half_rn(x0), __float2half_rn(x1));
            __half2 p23 = make_half2(__float2half_rn(x2), __float2half_rn(x3));
            aA[kc][2 * s + 0] = *reinterpret_cast<uint32_t*>(&p01);
            aA[kc][2 * s + 1] = *reinterpret_cast<uint32_t*>(&p23);
        }
    }

    // ---- phase 2: out = Q*Sp + A*V ----
    float o[2][2][4] = {};       // [col half][s][frag]
    #pragma unroll
    for (int ks = 0; ks < 2; ks++) {
        #pragma unroll
        for (int nh2 = 0; nh2 < 2; nh2++) {
            uint32_t fS[4], fV[4];
            ldsm4t(fS, smem_u32(&Ss[cw][(ks * 16 + (jA >> 1) * 8 + rA) * OS
                                        + nh2 * 16 + (jA & 1) * 8]));
            #pragma unroll
            for (int s = 0; s < 2; s++)
                mma16816(o[nh2][s], fQ[ks], fS[s], fS[s + 2]);
            ldsm4t(fV, smem_u32(&Vs[cw][(ks * 16 + (jA >> 1) * 8 + rA) * OS
                                        + nh2 * 16 + (jA & 1) * 8]));
            #pragma unroll
            for (int s = 0; s < 2; s++)
                mma16816(o[nh2][s], aA[ks], fV[s], fV[s + 2]);
        }
    }

    // ---- store fp32 ----
    #pragma unroll
    for (int nh2 = 0; nh2 < 2; nh2++) {
        #pragma unroll
        for (int s = 0; s < 2; s++) {
            int col = h * D_H + nh2 * 16 + s * 8 + 2 * ql;
            size_t ob0 = (size_t)(n * L_SEQ + c * CHUNK + row0) * DIM + col;
            size_t ob1 = (size_t)(n * L_SEQ + c * CHUNK + row0 + 8) * DIM + col;
            *reinterpret_cast<float2*>(&out[ob0]) = make_float2(o[nh2][s][0], o[nh2][s][1]);
            *reinterpret_cast<float2*>(&out[ob1]) = make_float2(o[nh2][s][2], o[nh2][s][3]);
        }
    }
}

// ---------------------------------------------------------------------------
extern "C" void kernel_launch(void* const* d_in, const int* in_sizes, int n_in,
                              void* d_out, int out_size)
{
    const float* query = (const float*)d_in[0];
    const float* key   = (const float*)d_in[1];
    const float* Wq    = (const float*)d_in[2];
    const float* Wk    = (const float*)d_in[3];
    const float* Wv    = (const float*)d_in[4];
    float* out = (float*)d_out;

    cudaFuncSetAttribute(proj_mma_kernel,
                         cudaFuncAttributeMaxDynamicSharedMemorySize, SMEM_BYTES);

    int conv_blocks = (2 * NQ4 + 3 * NW4) / 256;
    convert_kernel<<<conv_blocks, 256>>>(query, key, Wq, Wk, Wv);

    dim3 gp(DIM / 128, TOT_ROWS / 128, 3);      // (4, 64, 3) = 768 CTAs
    proj_mma_kernel<<<gp, 256, SMEM_BYTES>>>();

    chunk_kv_kernel<<<N_B * N_H * N_CHUNK, 128>>>();
    scan_kernel<<<(N_B * N_H * D_H * D_H) / 64, 256>>>();     // 1024 blocks
    out_mma_kernel<<<(N_B * N_H * N_CHUNK) / 2, 128>>>(out);  // 2048 blocks
}